// round 11
// baseline (speedup 1.0000x reference)
#include <cuda_runtime.h>
#include <cuda_fp16.h>
#include <math.h>
#include <stdint.h>

// Problem constants
#define BD   8
#define TD   2048
#define DD   512
#define NTOT (BD * TD)     // 16384
#define KTOT 4096          // D * P
#define NKC  64            // K-chunks of 64 elements
#define SEG  64
#define SEGLEN (TD / SEG)  // 32

// ---------------------------------------------------------------------------
// Scratch (device globals — no allocations allowed)
// ---------------------------------------------------------------------------
__device__ float g_s0[(size_t)DD * NTOT];
__device__ float g_s1[(size_t)DD * NTOT];
__device__ float g_zl[(size_t)NTOT * DD];
__device__ float g_hbar[(size_t)NTOT * DD];
// Pre-swizzled chunk tiles: [layer][nb(4)][kc(64)] each 16KB (128 rows x 64 cols fp16)
__device__ __half g_bt_hi[5][(size_t)4 * 64 * 8192];
// scan scratch
__device__ float g_scanA[BD * SEG * DD];
__device__ float g_scanB[BD * SEG * DD];
__device__ float g_scanH[BD * SEG * DD];

// ---------------------------------------------------------------------------
// helpers
// ---------------------------------------------------------------------------
__device__ __forceinline__ uint32_t smem_u32(const void* p) {
    uint32_t a;
    asm("{ .reg .u64 t; cvta.to.shared.u64 t, %1; cvt.u32.u64 %0, t; }"
        : "=r"(a) : "l"(p));
    return a;
}

#define SWZ(x) ((x) ^ (((x) >> 3) & 0x70))

__device__ __forceinline__ void mbar_init(uint32_t a, uint32_t cnt) {
    asm volatile("mbarrier.init.shared.b64 [%0], %1;" :: "r"(a), "r"(cnt) : "memory");
}

__device__ __forceinline__ void mbar_wait(uint32_t a, uint32_t ph) {
    asm volatile(
        "{\n\t.reg .pred P;\n\t"
        "W%=:\n\t"
        "mbarrier.try_wait.parity.acquire.cta.shared::cta.b64 P, [%0], %1, 0x989680;\n\t"
        "@P bra.uni D%=;\n\t"
        "bra.uni W%=;\n\t"
        "D%=:\n\t}"
        :: "r"(a), "r"(ph) : "memory");
}

__device__ __forceinline__ void mbar_expect_tx(uint32_t a, uint32_t bytes) {
    asm volatile("mbarrier.arrive.expect_tx.shared.b64 _, [%0], %1;"
                 :: "r"(a), "r"(bytes) : "memory");
}

__device__ __forceinline__ void bulk_ld(uint32_t dst, const void* src,
                                        uint32_t bytes, uint32_t mbar) {
    asm volatile(
        "cp.async.bulk.shared::cluster.global.mbarrier::complete_tx::bytes "
        "[%0], [%1], %2, [%3];"
        :: "r"(dst), "l"(src), "r"(bytes), "r"(mbar) : "memory");
}

// ---------------------------------------------------------------------------
// build_s (paired via blockIdx.z): s[i*N+n] = k + t
// ---------------------------------------------------------------------------
__global__ __launch_bounds__(256) void build_s_pair_kernel(
    const float* __restrict__ X, const float* __restrict__ P0,
    const float* __restrict__ P1, float* __restrict__ S0,
    float* __restrict__ S1, int N) {
    const float* Pp = blockIdx.z ? P1 : P0;
    float* S = blockIdx.z ? S1 : S0;
    __shared__ float tile[32][33];
    int i0 = blockIdx.x * 32;
    int n0 = blockIdx.y * 32;
    int tx = threadIdx.x;
    int ty = threadIdx.y;
    int i = i0 + tx;

    float p[8];
#pragma unroll
    for (int j = 0; j < 8; ++j) p[j] = Pp[i * 8 + j];

#pragma unroll
    for (int r = 0; r < 4; ++r) {
        int nl = ty + 8 * r;
        int n = n0 + nl;
        float x = X[(size_t)n * DD + i];
        int k = 0;
        float pl = p[0], pr = p[1];
#pragma unroll
        for (int j = 1; j <= 6; ++j) {
            if (p[j] < x) { k = j; pl = p[j]; pr = p[j + 1]; }
        }
        float t = (x - pl) / (pr - pl);
        t = fminf(fmaxf(t, 0.0f), 1.0f);
        tile[nl][tx] = (float)k + t;
    }
    __syncthreads();
#pragma unroll
    for (int r = 0; r < 4; ++r) {
        int il = ty + 8 * r;
        S[(size_t)(i0 + il) * N + n0 + tx] = tile[tx][il];
    }
}

// ---------------------------------------------------------------------------
// split_chunk: v (4096 x 512 f32) -> pre-swizzled 16KB chunk tiles, fp16.
// ---------------------------------------------------------------------------
__global__ __launch_bounds__(256) void split_chunk_kernel(
    const float* __restrict__ va, const float* __restrict__ vb,
    const float* __restrict__ vc, int ibase) {
    int kc = blockIdx.x, nb = blockIdx.y, z = blockIdx.z;
    const float* v = (z == 0) ? va : (z == 1) ? vb : vc;
    int layer = ibase + z;
    size_t tile_off = ((size_t)layer * 256 + nb * 64 + kc) << 14;  // bytes
    char* hib = (char*)g_bt_hi + tile_off;

    int r = threadIdx.x & 127;
    int chalf = threadIdx.x >> 7;
#pragma unroll
    for (int j = 0; j < 32; ++j) {
        int c = chalf * 32 + j;
        float val = v[(size_t)(kc * 64 + c) * DD + nb * 128 + r];
        uint32_t off = SWZ((uint32_t)(r * 128 + c * 2));
        *(__half*)(hib + off) = __float2half_rn(val);
    }
}

// ---------------------------------------------------------------------------
// APL sparse-HMMA GEMM: C has 2 nonzeros per 8-col i-block -> 2:4 sparsity.
// mma.sp::ordered_metadata.m16n8k32. 256 threads, 8 warps (2Mx4N),
// warp tile 64x32, CTA tile 128x128. B via cp.async.bulk (4-stage ring).
// A compressed tile: 128 rows x 32 storage halves (64B), 2 rows per 128B line.
// Metadata: 1 byte per (row, i) in SMEM (two 4-bit group nibbles).
// ---------------------------------------------------------------------------
#define TILE16K 16384
#define A_TILE  8192
#define M_TILE  1024
// layout: [slack 1024][MB 1024][ME 2x1024][A 2x8192][B 4x16384]
#define SMEM_REQ (1024 + 1024 + 2048 + 2 * A_TILE + 4 * TILE16K)

__device__ __forceinline__ void load_S4(const float* __restrict__ S, int bm,
                                        int kc, int tid, float* sv) {
#pragma unroll
    for (int q = 0; q < 4; ++q) {
        int idx = tid + 256 * q;
        int n = idx & 127;
        int il = idx >> 7;
        sv[q] = __ldg(&S[(size_t)(kc * 8 + il) * NTOT + bm + n]);
    }
}

// Build compressed A (2:4) + metadata for one chunk.
__device__ __forceinline__ void build_A_sp(const float* sv, uint32_t abase,
                                           uint32_t mbase, int tid) {
#pragma unroll
    for (int q4 = 0; q4 < 4; ++q4) {
        int idx = tid + 256 * q4;
        int n = idx & 127;    // row
        int il = idx >> 7;    // i within chunk, 0..7
        float svv = sv[q4];
        int k = min((int)svv, 6);
        float t = svv - (float)k;
        __half2 h2 = __floats2half2_rn(1.0f - t, t);   // low=cl, high=t
        uint32_t P = *(uint32_t*)&h2;
        uint32_t w0, w1, m0, m1;
        if (k <= 2)      { w0 = P;       w1 = 0u;      m0 = (uint32_t)(k | ((k + 1) << 2)); m1 = 4u; }
        else if (k == 3) { w0 = P << 16; w1 = P >> 16; m0 = 12u;                            m1 = 4u; }
        else             { int kp = k - 4; w0 = 0u; w1 = P; m0 = 4u;
                           m1 = (uint32_t)(kp | ((kp + 1) << 2)); }
        uint32_t off = (uint32_t)((n >> 1) * 128 + (n & 1) * 64 +
                                  (il >> 2) * 32 + (il & 3) * 8);
        asm volatile("st.shared.v2.b32 [%0], {%1,%2};"
                     :: "r"(abase + SWZ(off)), "r"(w0), "r"(w1) : "memory");
        uint32_t mb = m0 | (m1 << 4);
        asm volatile("st.shared.u8 [%0], %1;"
                     :: "r"(mbase + (uint32_t)(n * 8 + il)), "r"(mb) : "memory");
    }
}

__device__ __forceinline__ void ldsm4(uint32_t a, uint32_t& r0, uint32_t& r1,
                                      uint32_t& r2, uint32_t& r3) {
    asm volatile("ldmatrix.sync.aligned.m8n8.x4.shared.b16 {%0,%1,%2,%3}, [%4];"
                 : "=r"(r0), "=r"(r1), "=r"(r2), "=r"(r3) : "r"(a));
}

__device__ __forceinline__ void mmasp(float* d, const uint32_t* a,
                                      const uint32_t* b, uint32_t e) {
    asm volatile(
        "mma.sp::ordered_metadata.sync.aligned.m16n8k32.row.col.f32.f16.f16.f32 "
        "{%0,%1,%2,%3}, {%4,%5,%6,%7}, {%8,%9,%10,%11}, {%0,%1,%2,%3}, %12, 0x0;"
        : "+f"(d[0]), "+f"(d[1]), "+f"(d[2]), "+f"(d[3])
        : "r"(a[0]), "r"(a[1]), "r"(a[2]), "r"(a[3]),
          "r"(b[0]), "r"(b[1]), "r"(b[2]), "r"(b[3]), "r"(e));
}

__global__ void __launch_bounds__(256, 2) apl_hmma_kernel(
    const float* __restrict__ S0, const float* __restrict__ S1,
    const __half* __restrict__ Bhi0, const __half* __restrict__ Bhi1,
    float* __restrict__ out0, float* __restrict__ out1) {
    const int zz = blockIdx.z;
    const float* S = zz ? S1 : S0;
    const __half* Bhi = zz ? Bhi1 : Bhi0;
    float* out = zz ? out1 : out0;

    extern __shared__ char smem[];
    uint32_t sb = (smem_u32(smem) + 1023u) & ~1023u;
    const uint32_t MB = sb;                    // 4 mbarriers
    const uint32_t ME = sb + 1024;             // 2 x 1KB metadata
    const uint32_t AH = sb + 3072;             // 2 x 8KB compressed A
    const uint32_t BH = sb + 3072 + 2 * A_TILE;  // 4 x 16KB B
    const int tid = threadIdx.x;
    const int lane = tid & 31;
    const int wid = tid >> 5;
    const int wm = wid & 1;             // 2 warp rows (64 each)
    const int wn = wid >> 1;            // 4 warp cols (32 each)
    const int bm = blockIdx.x * 128;
    const int nb = blockIdx.y;

    const char* hsrc = (const char*)Bhi + ((size_t)nb * 64 << 14);

    if (tid == 0) {
        mbar_init(MB + 0, 1);
        mbar_init(MB + 8, 1);
        mbar_init(MB + 16, 1);
        mbar_init(MB + 24, 1);
        asm volatile("fence.proxy.async.shared::cta;" ::: "memory");
    }
    __syncthreads();

    float acc[4][4][4];
#pragma unroll
    for (int mi = 0; mi < 4; ++mi)
#pragma unroll
        for (int nj = 0; nj < 4; ++nj)
#pragma unroll
            for (int u = 0; u < 4; ++u) acc[mi][nj][u] = 0.0f;

    uint32_t a_off[4], b_off[2];
#pragma unroll
    for (int mi = 0; mi < 4; ++mi) {
        int arow = wm * 64 + mi * 16 + (lane & 15);
        a_off[mi] = (uint32_t)((arow >> 1) * 128 + (arow & 1) * 64 +
                               (lane >> 4) * 16);
    }
#pragma unroll
    for (int ni = 0; ni < 2; ++ni) {
        int row = wn * 32 + ni * 16 + (lane & 7) + ((lane & 16) >> 1);
        b_off[ni] = (uint32_t)(row * 128 + ((lane >> 3) & 1) * 16);
    }
    // metadata base offset for this thread (rows g, g+8; k-half by lane parity)
    const uint32_t me_t = (uint32_t)((wm * 64 + (lane >> 2)) * 8 + (lane & 1) * 2);

    // prologue: B chunks 0..2 in flight; A(0)+meta built; S(1) in regs
    if (tid == 0) {
#pragma unroll
        for (int c = 0; c < 3; ++c) {
            mbar_expect_tx(MB + c * 8, TILE16K);
            bulk_ld(BH + c * TILE16K, hsrc + ((size_t)c << 14), TILE16K, MB + c * 8);
        }
    }
    float sv_cur[4], sv_nxt[4];
    load_S4(S, bm, 0, tid, sv_cur);
    build_A_sp(sv_cur, AH, ME, tid);
    load_S4(S, bm, 1, tid, sv_nxt);

    for (int kc = 0; kc < NKC; ++kc) {
        int st = kc & 3;
        uint32_t parity = (uint32_t)((kc >> 2) & 1);
        mbar_wait(MB + st * 8, parity);
        __syncthreads();   // B(kc) ready; A(kc)+meta built; stage (kc+3)&3 free

        if (tid == 0 && kc + 3 < NKC) {
            int s2 = (kc + 3) & 3;
            mbar_expect_tx(MB + s2 * 8, TILE16K);
            bulk_ld(BH + s2 * TILE16K, hsrc + ((size_t)(kc + 3) << 14), TILE16K,
                    MB + s2 * 8);
        }

        const uint32_t AHc = AH + (kc & 1) * A_TILE;
        const uint32_t MEc = ME + (kc & 1) * M_TILE;
        const uint32_t BHc = BH + st * TILE16K;

        // hoist metadata regs: rows (R, R+8) -> (low16, high16)
        uint32_t metar[4][2];
#pragma unroll
        for (int mi = 0; mi < 4; ++mi)
#pragma unroll
            for (int q = 0; q < 2; ++q) {
                uint32_t base = MEc + me_t + (uint32_t)(mi * 16 * 8 + q * 4);
                uint32_t lo_, hi_;
                asm volatile("ld.shared.u16 %0, [%1];" : "=r"(lo_) : "r"(base));
                asm volatile("ld.shared.u16 %0, [%1];" : "=r"(hi_) : "r"(base + 64));
                metar[mi][q] = lo_ | (hi_ << 16);
            }

#pragma unroll
        for (int q = 0; q < 2; ++q) {
            uint32_t asp[4][4], bsp[4][4];
#pragma unroll
            for (int mi = 0; mi < 4; ++mi)
                ldsm4(AHc + SWZ(a_off[mi] + q * 32),
                      asp[mi][0], asp[mi][1], asp[mi][2], asp[mi][3]);
#pragma unroll
            for (int ni = 0; ni < 2; ++ni) {
                uint32_t r0, r1, r2, r3;
                ldsm4(BHc + SWZ(b_off[ni] + (2 * q) * 32), r0, r1, r2, r3);
                bsp[2 * ni][0] = r0; bsp[2 * ni][1] = r1;
                bsp[2 * ni + 1][0] = r2; bsp[2 * ni + 1][1] = r3;
                ldsm4(BHc + SWZ(b_off[ni] + (2 * q + 1) * 32), r0, r1, r2, r3);
                bsp[2 * ni][2] = r0; bsp[2 * ni][3] = r1;
                bsp[2 * ni + 1][2] = r2; bsp[2 * ni + 1][3] = r3;
            }
#pragma unroll
            for (int mi = 0; mi < 4; ++mi)
#pragma unroll
                for (int nj = 0; nj < 4; ++nj)
                    mmasp(acc[mi][nj], asp[mi], bsp[nj], metar[mi][q]);
        }

        // build A(kc+1)+meta from prefetched regs, then prefetch S(kc+2)
        if (kc + 1 < NKC) {
            build_A_sp(sv_nxt, AH + ((kc + 1) & 1) * A_TILE,
                       ME + ((kc + 1) & 1) * M_TILE, tid);
            if (kc + 2 < NKC)
                load_S4(S, bm, kc + 2, tid, sv_nxt);
        }
    }

    // epilogue
#pragma unroll
    for (int mi = 0; mi < 4; ++mi) {
#pragma unroll
        for (int nj = 0; nj < 4; ++nj) {
            int row = bm + wm * 64 + mi * 16 + (lane >> 2);
            int col = nb * 128 + wn * 32 + nj * 8 + 2 * (lane & 3);
            float2* p0 = (float2*)&out[(size_t)row * DD + col];
            float2* p1 = (float2*)&out[(size_t)(row + 8) * DD + col];
            *p0 = make_float2(acc[mi][nj][0], acc[mi][nj][1]);
            *p1 = make_float2(acc[mi][nj][2], acc[mi][nj][3]);
        }
    }
}

// ---------------------------------------------------------------------------
// Segmented scan, SEG=64. p1/p2/p3+norm as before.
// ---------------------------------------------------------------------------
__global__ __launch_bounds__(256) void scan_p1(
    const float* __restrict__ zl, const float* __restrict__ hb) {
    int gid = blockIdx.x * blockDim.x + threadIdx.x;
    if (gid >= BD * SEG * DD) return;
    int d = gid & 511;
    int bs = gid >> 9;
    int seg = bs & (SEG - 1);
    int b = bs / SEG;
    size_t base = (size_t)b * TD * DD + (size_t)seg * SEGLEN * DD + d;
    float A = 1.0f, Bv = 0.0f;
#pragma unroll 8
    for (int t = 0; t < SEGLEN; ++t) {
        size_t idx = base + (size_t)t * DD;
        float zv = 1.0f / (1.0f + expf(-zl[idx]));
        float a = 1.0f - zv;
        float bb = zv * hb[idx];
        A *= a;
        Bv = fmaf(a, Bv, bb);
    }
    g_scanA[gid] = A;
    g_scanB[gid] = Bv;
}

__global__ __launch_bounds__(256) void scan_p2() {
    int c = blockIdx.x * blockDim.x + threadIdx.x;
    if (c >= BD * DD) return;
    int d = c & 511;
    int b = c >> 9;
    float h = 0.0f;
#pragma unroll
    for (int seg = 0; seg < SEG; ++seg) {
        int gid = ((b * SEG + seg) << 9) + d;
        g_scanH[gid] = h;
        h = fmaf(g_scanA[gid], h, g_scanB[gid]);
    }
}

__global__ __launch_bounds__(512) void scan_p3_norm(
    const float* __restrict__ zl, const float* __restrict__ hb,
    float* __restrict__ h) {
    __shared__ float red[34];
    int blk = blockIdx.x;
    int d = threadIdx.x;
    int seg = blk & (SEG - 1);
    int b = blk / SEG;
    int lane = d & 31, wid = d >> 5;
    size_t base = (size_t)b * TD * DD + (size_t)seg * SEGLEN * DD + d;
    float hc = g_scanH[(blk << 9) + d];

    for (int t = 0; t < SEGLEN; ++t) {
        size_t idx = base + (size_t)t * DD;
        float zv = 1.0f / (1.0f + expf(-zl[idx]));
        hc = fmaf(zv, hb[idx] - hc, hc);
        int slot = (t & 1) * 17;
        float m = fabsf(hc);
#pragma unroll
        for (int o = 16; o; o >>= 1)
            m = fmaxf(m, __shfl_xor_sync(0xffffffffu, m, o));
        if (lane == 0) red[slot + wid] = m;
        __syncthreads();
        if (wid == 0) {
            float mm = red[slot + (lane & 15)];
#pragma unroll
            for (int o = 8; o; o >>= 1)
                mm = fmaxf(mm, __shfl_xor_sync(0xffffffffu, mm, o));
            if (lane == 0) red[slot + 16] = mm;
        }
        __syncthreads();
        float inv = 1.0f / (red[slot + 16] + 1e-6f);
        h[idx] = hc * inv;
    }
}

// ---------------------------------------------------------------------------
// kernel_launch (launch #4 = paired apl_hmma for the ncu capture window)
// ---------------------------------------------------------------------------
extern "C" void kernel_launch(void* const* d_in, const int* in_sizes, int n_in,
                              void* d_out, int out_size) {
    const float* x   = (const float*)d_in[0];
    const float* pz0 = (const float*)d_in[1];
    const float* vz0 = (const float*)d_in[2];
    const float* ph0 = (const float*)d_in[3];
    const float* vh0 = (const float*)d_in[4];
    const float* pz1 = (const float*)d_in[5];
    const float* vz1 = (const float*)d_in[6];
    const float* ph1 = (const float*)d_in[7];
    const float* vh1 = (const float*)d_in[8];
    const float* po  = (const float*)d_in[9];
    const float* vo  = (const float*)d_in[10];

    const int N = in_sizes[0] / DD;  // 16384

    float *s0, *s1, *zl, *hb;
    __half *bhi;
    cudaGetSymbolAddress((void**)&s0, g_s0);
    cudaGetSymbolAddress((void**)&s1, g_s1);
    cudaGetSymbolAddress((void**)&zl, g_zl);
    cudaGetSymbolAddress((void**)&hb, g_hbar);
    cudaGetSymbolAddress((void**)&bhi, g_bt_hi);

    static int smem_set = 0;
    if (!smem_set) {
        cudaFuncSetAttribute(apl_hmma_kernel,
                             cudaFuncAttributeMaxDynamicSharedMemorySize, SMEM_REQ);
        smem_set = 1;
    }

    float* out = (float*)d_out;
    float* h1  = out + (size_t)N * DD;
    float* h2  = h1 + (size_t)N * DD;

    dim3 tgrid(DD / 32, N / 32, 2);
    dim3 tblk(32, 8);
    dim3 sp3(64, 4, 3);
    dim3 sp2(64, 4, 2);
    dim3 gpair(N / 128, DD / 128, 2);
    dim3 gone(N / 128, DD / 128, 1);
    const int p1_blocks = (BD * SEG * DD + 255) / 256;
    const int p2_blocks = (BD * DD + 255) / 256;
    const int p3_blocks = BD * SEG;
    const size_t LSZ = (size_t)4 * 64 * 8192;

    // [1][2] pre-stage all V into chunked/pre-swizzled fp16 tiles
    split_chunk_kernel<<<sp3, 256>>>(vz0, vh0, vz1, 0);
    split_chunk_kernel<<<sp2, 256>>>(vh1, vo, vo, 3);

    // ---- layer 0 ----
    build_s_pair_kernel<<<tgrid, tblk>>>(x, pz0, ph0, s0, s1, N);            // [3]
    apl_hmma_kernel<<<gpair, 256, SMEM_REQ>>>(s0, s1, bhi + 0 * LSZ,
                                              bhi + 1 * LSZ, zl, hb);        // [4] profiled
    scan_p1<<<p1_blocks, 256>>>(zl, hb);
    scan_p2<<<p2_blocks, 256>>>();
    scan_p3_norm<<<p3_blocks, 512>>>(zl, hb, h1);

    // ---- layer 1 ----
    build_s_pair_kernel<<<tgrid, tblk>>>(h1, pz1, ph1, s0, s1, N);
    apl_hmma_kernel<<<gpair, 256, SMEM_REQ>>>(s0, s1, bhi + 2 * LSZ,
                                              bhi + 3 * LSZ, zl, hb);
    scan_p1<<<p1_blocks, 256>>>(zl, hb);
    scan_p2<<<p2_blocks, 256>>>();
    scan_p3_norm<<<p3_blocks, 512>>>(zl, hb, h2);

    // ---- output APL ----
    build_s_pair_kernel<<<dim3(DD / 32, N / 32, 1), tblk>>>(h2, po, po, s0, s1, N);
    apl_hmma_kernel<<<gone, 256, SMEM_REQ>>>(s0, s0, bhi + 4 * LSZ,
                                             bhi + 4 * LSZ, out, out);
}

// round 12
// speedup vs baseline: 1.1927x; 1.1927x over previous
#include <cuda_runtime.h>
#include <cuda_fp16.h>
#include <math.h>
#include <stdint.h>

// Problem constants
#define BD   8
#define TD   2048
#define DD   512
#define NTOT (BD * TD)     // 16384
#define KTOT 4096          // D * P
#define NKC  64            // K-chunks of 64 elements
#define NMT  128           // M-tiles of 128 rows
#define SEG  64
#define SEGLEN (TD / SEG)  // 32

// ---------------------------------------------------------------------------
// Scratch (device globals — no allocations allowed)
// ---------------------------------------------------------------------------
__device__ float g_zl[(size_t)NTOT * DD];
__device__ float g_hbar[(size_t)NTOT * DD];
// Pre-swizzled B chunk tiles: [layer][nb(4)][kc(64)] 16KB each
__device__ __align__(128) __half g_bt_hi[5][(size_t)4 * 64 * 8192];
// Compressed 2:4 A tiles: [inst(2)][mt(128)][kc(64)] 8KB each (+1KB metadata)
__device__ __align__(128) __half   g_A[2][(size_t)NMT * NKC * 4096];
__device__ __align__(128) uint8_t g_MM[2][(size_t)NMT * NKC * 1024];
// scan scratch
__device__ float g_scanA[BD * SEG * DD];
__device__ float g_scanB[BD * SEG * DD];
__device__ float g_scanH[BD * SEG * DD];

// ---------------------------------------------------------------------------
// helpers
// ---------------------------------------------------------------------------
__device__ __forceinline__ uint32_t smem_u32(const void* p) {
    uint32_t a;
    asm("{ .reg .u64 t; cvta.to.shared.u64 t, %1; cvt.u32.u64 %0, t; }"
        : "=r"(a) : "l"(p));
    return a;
}

#define SWZ(x) ((x) ^ (((x) >> 3) & 0x70))

__device__ __forceinline__ void mbar_init(uint32_t a, uint32_t cnt) {
    asm volatile("mbarrier.init.shared.b64 [%0], %1;" :: "r"(a), "r"(cnt) : "memory");
}

__device__ __forceinline__ void mbar_wait(uint32_t a, uint32_t ph) {
    asm volatile(
        "{\n\t.reg .pred P;\n\t"
        "W%=:\n\t"
        "mbarrier.try_wait.parity.acquire.cta.shared::cta.b64 P, [%0], %1, 0x989680;\n\t"
        "@P bra.uni D%=;\n\t"
        "bra.uni W%=;\n\t"
        "D%=:\n\t}"
        :: "r"(a), "r"(ph) : "memory");
}

__device__ __forceinline__ void mbar_expect_tx(uint32_t a, uint32_t bytes) {
    asm volatile("mbarrier.arrive.expect_tx.shared.b64 _, [%0], %1;"
                 :: "r"(a), "r"(bytes) : "memory");
}

__device__ __forceinline__ void bulk_ld(uint32_t dst, const void* src,
                                        uint32_t bytes, uint32_t mbar) {
    asm volatile(
        "cp.async.bulk.shared::cluster.global.mbarrier::complete_tx::bytes "
        "[%0], [%1], %2, [%3];"
        :: "r"(dst), "l"(src), "r"(bytes), "r"(mbar) : "memory");
}

// ---------------------------------------------------------------------------
// split_chunk: v (4096 x 512 f32) -> pre-swizzled 16KB B chunk tiles, fp16.
// ---------------------------------------------------------------------------
__global__ __launch_bounds__(256) void split_chunk_kernel(
    const float* __restrict__ va, const float* __restrict__ vb,
    const float* __restrict__ vc, int ibase) {
    int kc = blockIdx.x, nb = blockIdx.y, z = blockIdx.z;
    const float* v = (z == 0) ? va : (z == 1) ? vb : vc;
    int layer = ibase + z;
    size_t tile_off = ((size_t)layer * 256 + nb * 64 + kc) << 14;  // bytes
    char* hib = (char*)g_bt_hi + tile_off;

    int r = threadIdx.x & 127;
    int chalf = threadIdx.x >> 7;
#pragma unroll
    for (int j = 0; j < 32; ++j) {
        int c = chalf * 32 + j;
        float val = v[(size_t)(kc * 64 + c) * DD + nb * 128 + r];
        uint32_t off = SWZ((uint32_t)(r * 128 + c * 2));
        *(__half*)(hib + off) = __float2half_rn(val);
    }
}

// ---------------------------------------------------------------------------
// build_A_kernel: fused searchsorted + hat + 2:4 compression.
// Writes pre-swizzled compressed A tiles (8KB) + metadata (1KB) per
// (mtile, kc) to global, chunk-contiguous for bulk DMA.
// grid (NMT, NKC, ninst); block 256; thread il fixed = tid&7.
// ---------------------------------------------------------------------------
__global__ __launch_bounds__(256) void build_A_kernel(
    const float* __restrict__ X, const float* __restrict__ P0,
    const float* __restrict__ P1) {
    int mt = blockIdx.x, kc = blockIdx.y, z = blockIdx.z;
    const float* Pp = z ? P1 : P0;
    char* Ab = (char*)g_A[z] + ((size_t)(mt * NKC + kc) << 13);
    uint8_t* Mb = g_MM[z] + ((size_t)(mt * NKC + kc) << 10);
    int tid = threadIdx.x;
    int il = tid & 7;
    int i = kc * 8 + il;
    float p[8];
#pragma unroll
    for (int j = 0; j < 8; ++j) p[j] = __ldg(&Pp[i * 8 + j]);
    int bm = mt * 128;
#pragma unroll
    for (int q = 0; q < 4; ++q) {
        int n = (tid >> 3) + 32 * q;
        float x = __ldg(&X[(size_t)(bm + n) * DD + i]);
        int k = 0;
        float pl = p[0], pr = p[1];
#pragma unroll
        for (int j = 1; j <= 6; ++j)
            if (p[j] < x) { k = j; pl = p[j]; pr = p[j + 1]; }
        float t = fminf(fmaxf((x - pl) / (pr - pl), 0.0f), 1.0f);
        __half2 h2 = __floats2half2_rn(1.0f - t, t);
        uint32_t P = *(uint32_t*)&h2;
        uint32_t w0, w1, m0, m1;
        if (k <= 2)      { w0 = P;       w1 = 0u;      m0 = (uint32_t)(k | ((k + 1) << 2)); m1 = 4u; }
        else if (k == 3) { w0 = P << 16; w1 = P >> 16; m0 = 12u;                            m1 = 4u; }
        else             { int kp = k - 4; w0 = 0u; w1 = P; m0 = 4u;
                           m1 = (uint32_t)(kp | ((kp + 1) << 2)); }
        uint32_t off = (uint32_t)((n >> 1) * 128 + (n & 1) * 64 +
                                  (il >> 2) * 32 + (il & 3) * 8);
        *(uint2*)(Ab + SWZ(off)) = make_uint2(w0, w1);
        Mb[n * 8 + il] = (uint8_t)(m0 | (m1 << 4));
    }
}

// ---------------------------------------------------------------------------
// APL sparse-HMMA GEMM. Everything (A compressed, metadata, B) streamed via
// cp.async.bulk into a 4-stage ring. 256 threads, 8 warps (2Mx4N),
// warp tile 64x32, CTA tile 128x128, 2 CTA/SM.
// Stage unit 25600B: [A 8192][meta 1024][B 16384]
// ---------------------------------------------------------------------------
#define STAGE_SZ 25600
#define SMEM_REQ (1024 + 1024 + 4 * STAGE_SZ)

__device__ __forceinline__ void ldsm4(uint32_t a, uint32_t& r0, uint32_t& r1,
                                      uint32_t& r2, uint32_t& r3) {
    asm volatile("ldmatrix.sync.aligned.m8n8.x4.shared.b16 {%0,%1,%2,%3}, [%4];"
                 : "=r"(r0), "=r"(r1), "=r"(r2), "=r"(r3) : "r"(a));
}

__device__ __forceinline__ void mmasp(float* d, const uint32_t* a,
                                      const uint32_t* b, uint32_t e) {
    asm volatile(
        "mma.sp::ordered_metadata.sync.aligned.m16n8k32.row.col.f32.f16.f16.f32 "
        "{%0,%1,%2,%3}, {%4,%5,%6,%7}, {%8,%9,%10,%11}, {%0,%1,%2,%3}, %12, 0x0;"
        : "+f"(d[0]), "+f"(d[1]), "+f"(d[2]), "+f"(d[3])
        : "r"(a[0]), "r"(a[1]), "r"(a[2]), "r"(a[3]),
          "r"(b[0]), "r"(b[1]), "r"(b[2]), "r"(b[3]), "r"(e));
}

__global__ void __launch_bounds__(256, 2) apl_hmma_kernel(
    const __half* __restrict__ A0, const uint8_t* __restrict__ M0,
    const __half* __restrict__ A1, const uint8_t* __restrict__ M1,
    const __half* __restrict__ B0, const __half* __restrict__ B1,
    float* __restrict__ out0, float* __restrict__ out1) {
    const int zz = blockIdx.z;
    const char* aSrc = (const char*)(zz ? A1 : A0);
    const char* mSrc = (const char*)(zz ? M1 : M0);
    const __half* Bhi = zz ? B1 : B0;
    float* out = zz ? out1 : out0;

    extern __shared__ char smem[];
    uint32_t sb = (smem_u32(smem) + 1023u) & ~1023u;
    const uint32_t MB = sb;                 // 4 mbarriers
    const uint32_t ST = sb + 1024;          // 4 x STAGE_SZ
    const int tid = threadIdx.x;
    const int lane = tid & 31;
    const int wid = tid >> 5;
    const int wm = wid & 1;             // 2 warp rows (64 each)
    const int wn = wid >> 1;            // 4 warp cols (32 each)
    const int mt = blockIdx.x;
    const int nb = blockIdx.y;

    const char* bsrc = (const char*)Bhi + ((size_t)nb * 64 << 14);
    const size_t atile0 = (size_t)mt * NKC;

    if (tid == 0) {
        mbar_init(MB + 0, 1);
        mbar_init(MB + 8, 1);
        mbar_init(MB + 16, 1);
        mbar_init(MB + 24, 1);
        asm volatile("fence.proxy.async.shared::cta;" ::: "memory");
    }
    __syncthreads();

    float acc[4][4][4];
#pragma unroll
    for (int mi = 0; mi < 4; ++mi)
#pragma unroll
        for (int nj = 0; nj < 4; ++nj)
#pragma unroll
            for (int u = 0; u < 4; ++u) acc[mi][nj][u] = 0.0f;

    uint32_t a_off[4], b_off[2];
#pragma unroll
    for (int mi = 0; mi < 4; ++mi) {
        int arow = wm * 64 + mi * 16 + (lane & 15);
        a_off[mi] = (uint32_t)((arow >> 1) * 128 + (arow & 1) * 64 +
                               (lane >> 4) * 16);
    }
#pragma unroll
    for (int ni = 0; ni < 2; ++ni) {
        int row = wn * 32 + ni * 16 + (lane & 7) + ((lane & 16) >> 1);
        b_off[ni] = (uint32_t)(row * 128 + ((lane >> 3) & 1) * 16);
    }
    const uint32_t me_t = (uint32_t)((wm * 64 + (lane >> 2)) * 8 + (lane & 1) * 2);

    // prologue: stages 0..2 in flight
    if (tid == 0) {
#pragma unroll
        for (int c = 0; c < 3; ++c) {
            uint32_t stb = ST + c * STAGE_SZ;
            mbar_expect_tx(MB + c * 8, STAGE_SZ);
            bulk_ld(stb, aSrc + ((atile0 + c) << 13), 8192, MB + c * 8);
            bulk_ld(stb + 8192, mSrc + ((atile0 + c) << 10), 1024, MB + c * 8);
            bulk_ld(stb + 9216, bsrc + ((size_t)c << 14), 16384, MB + c * 8);
        }
    }

    for (int kc = 0; kc < NKC; ++kc) {
        int st = kc & 3;
        uint32_t parity = (uint32_t)((kc >> 2) & 1);
        mbar_wait(MB + st * 8, parity);
        __syncthreads();   // stage(kc) ready; all warps done with stage (kc+3)&3

        if (tid == 0 && kc + 3 < NKC) {
            int s2 = (kc + 3) & 3;
            uint32_t stb = ST + s2 * STAGE_SZ;
            mbar_expect_tx(MB + s2 * 8, STAGE_SZ);
            bulk_ld(stb, aSrc + ((atile0 + kc + 3) << 13), 8192, MB + s2 * 8);
            bulk_ld(stb + 8192, mSrc + ((atile0 + kc + 3) << 10), 1024, MB + s2 * 8);
            bulk_ld(stb + 9216, bsrc + ((size_t)(kc + 3) << 14), 16384, MB + s2 * 8);
        }

        const uint32_t AHc = ST + st * STAGE_SZ;
        const uint32_t MEc = AHc + 8192;
        const uint32_t BHc = AHc + 9216;

        // metadata regs: rows (R, R+8) -> (low16, high16)
        uint32_t metar[4][2];
#pragma unroll
        for (int mi = 0; mi < 4; ++mi)
#pragma unroll
            for (int q = 0; q < 2; ++q) {
                uint32_t base = MEc + me_t + (uint32_t)(mi * 128 + q * 4);
                uint32_t lo_, hi_;
                asm volatile("ld.shared.u16 %0, [%1];" : "=r"(lo_) : "r"(base));
                asm volatile("ld.shared.u16 %0, [%1];" : "=r"(hi_) : "r"(base + 64));
                metar[mi][q] = lo_ | (hi_ << 16);
            }

#pragma unroll
        for (int q = 0; q < 2; ++q) {
            uint32_t asp[4][4], bsp[4][4];
#pragma unroll
            for (int mi = 0; mi < 4; ++mi)
                ldsm4(AHc + SWZ(a_off[mi] + q * 32),
                      asp[mi][0], asp[mi][1], asp[mi][2], asp[mi][3]);
#pragma unroll
            for (int ni = 0; ni < 2; ++ni) {
                uint32_t r0, r1, r2, r3;
                ldsm4(BHc + SWZ(b_off[ni] + (2 * q) * 32), r0, r1, r2, r3);
                bsp[2 * ni][0] = r0; bsp[2 * ni][1] = r1;
                bsp[2 * ni + 1][0] = r2; bsp[2 * ni + 1][1] = r3;
                ldsm4(BHc + SWZ(b_off[ni] + (2 * q + 1) * 32), r0, r1, r2, r3);
                bsp[2 * ni][2] = r0; bsp[2 * ni][3] = r1;
                bsp[2 * ni + 1][2] = r2; bsp[2 * ni + 1][3] = r3;
            }
#pragma unroll
            for (int mi = 0; mi < 4; ++mi)
#pragma unroll
                for (int nj = 0; nj < 4; ++nj)
                    mmasp(acc[mi][nj], asp[mi], bsp[nj], metar[mi][q]);
        }
    }

    // epilogue
#pragma unroll
    for (int mi = 0; mi < 4; ++mi) {
#pragma unroll
        for (int nj = 0; nj < 4; ++nj) {
            int row = mt * 128 + wm * 64 + mi * 16 + (lane >> 2);
            int col = nb * 128 + wn * 32 + nj * 8 + 2 * (lane & 3);
            float2* p0 = (float2*)&out[(size_t)row * DD + col];
            float2* p1 = (float2*)&out[(size_t)(row + 8) * DD + col];
            *p0 = make_float2(acc[mi][nj][0], acc[mi][nj][1]);
            *p1 = make_float2(acc[mi][nj][2], acc[mi][nj][3]);
        }
    }
}

// ---------------------------------------------------------------------------
// Segmented scan, SEG=64. p1/p2/p3+norm.
// ---------------------------------------------------------------------------
__global__ __launch_bounds__(256) void scan_p1(
    const float* __restrict__ zl, const float* __restrict__ hb) {
    int gid = blockIdx.x * blockDim.x + threadIdx.x;
    if (gid >= BD * SEG * DD) return;
    int d = gid & 511;
    int bs = gid >> 9;
    int seg = bs & (SEG - 1);
    int b = bs / SEG;
    size_t base = (size_t)b * TD * DD + (size_t)seg * SEGLEN * DD + d;
    float A = 1.0f, Bv = 0.0f;
#pragma unroll 8
    for (int t = 0; t < SEGLEN; ++t) {
        size_t idx = base + (size_t)t * DD;
        float zv = 1.0f / (1.0f + expf(-zl[idx]));
        float a = 1.0f - zv;
        float bb = zv * hb[idx];
        A *= a;
        Bv = fmaf(a, Bv, bb);
    }
    g_scanA[gid] = A;
    g_scanB[gid] = Bv;
}

__global__ __launch_bounds__(256) void scan_p2() {
    int c = blockIdx.x * blockDim.x + threadIdx.x;
    if (c >= BD * DD) return;
    int d = c & 511;
    int b = c >> 9;
    float h = 0.0f;
#pragma unroll
    for (int seg = 0; seg < SEG; ++seg) {
        int gid = ((b * SEG + seg) << 9) + d;
        g_scanH[gid] = h;
        h = fmaf(g_scanA[gid], h, g_scanB[gid]);
    }
}

__global__ __launch_bounds__(512) void scan_p3_norm(
    const float* __restrict__ zl, const float* __restrict__ hb,
    float* __restrict__ h) {
    __shared__ float red[34];
    int blk = blockIdx.x;
    int d = threadIdx.x;
    int seg = blk & (SEG - 1);
    int b = blk / SEG;
    int lane = d & 31, wid = d >> 5;
    size_t base = (size_t)b * TD * DD + (size_t)seg * SEGLEN * DD + d;
    float hc = g_scanH[(blk << 9) + d];

    for (int t = 0; t < SEGLEN; ++t) {
        size_t idx = base + (size_t)t * DD;
        float zv = 1.0f / (1.0f + expf(-zl[idx]));
        hc = fmaf(zv, hb[idx] - hc, hc);
        int slot = (t & 1) * 17;
        float m = fabsf(hc);
#pragma unroll
        for (int o = 16; o; o >>= 1)
            m = fmaxf(m, __shfl_xor_sync(0xffffffffu, m, o));
        if (lane == 0) red[slot + wid] = m;
        __syncthreads();
        if (wid == 0) {
            float mm = red[slot + (lane & 15)];
#pragma unroll
            for (int o = 8; o; o >>= 1)
                mm = fmaxf(mm, __shfl_xor_sync(0xffffffffu, mm, o));
            if (lane == 0) red[slot + 16] = mm;
        }
        __syncthreads();
        float inv = 1.0f / (red[slot + 16] + 1e-6f);
        h[idx] = hc * inv;
    }
}

// ---------------------------------------------------------------------------
// kernel_launch (launch #4 = paired apl_hmma for the ncu capture window)
// ---------------------------------------------------------------------------
extern "C" void kernel_launch(void* const* d_in, const int* in_sizes, int n_in,
                              void* d_out, int out_size) {
    const float* x   = (const float*)d_in[0];
    const float* pz0 = (const float*)d_in[1];
    const float* vz0 = (const float*)d_in[2];
    const float* ph0 = (const float*)d_in[3];
    const float* vh0 = (const float*)d_in[4];
    const float* pz1 = (const float*)d_in[5];
    const float* vz1 = (const float*)d_in[6];
    const float* ph1 = (const float*)d_in[7];
    const float* vh1 = (const float*)d_in[8];
    const float* po  = (const float*)d_in[9];
    const float* vo  = (const float*)d_in[10];

    const int N = in_sizes[0] / DD;  // 16384

    float *zl, *hb;
    __half *bhi, *a0, *a1;
    uint8_t *m0, *m1;
    cudaGetSymbolAddress((void**)&zl, g_zl);
    cudaGetSymbolAddress((void**)&hb, g_hbar);
    cudaGetSymbolAddress((void**)&bhi, g_bt_hi);
    cudaGetSymbolAddress((void**)&a0, g_A);
    cudaGetSymbolAddress((void**)&m0, g_MM);
    a1 = a0 + (size_t)NMT * NKC * 4096;
    m1 = m0 + (size_t)NMT * NKC * 1024;

    static int smem_set = 0;
    if (!smem_set) {
        cudaFuncSetAttribute(apl_hmma_kernel,
                             cudaFuncAttributeMaxDynamicSharedMemorySize, SMEM_REQ);
        smem_set = 1;
    }

    float* out = (float*)d_out;
    float* h1  = out + (size_t)N * DD;
    float* h2  = h1 + (size_t)N * DD;

    dim3 sp3(64, 4, 3);
    dim3 sp2(64, 4, 2);
    dim3 agrid2(NMT, NKC, 2);
    dim3 agrid1(NMT, NKC, 1);
    dim3 gpair(NMT, 4, 2);
    dim3 gone(NMT, 4, 1);
    const int p1_blocks = (BD * SEG * DD + 255) / 256;
    const int p2_blocks = (BD * DD + 255) / 256;
    const int p3_blocks = BD * SEG;
    const size_t LSZ = (size_t)4 * 64 * 8192;

    // [1][2] pre-stage all V into chunked/pre-swizzled fp16 B tiles
    split_chunk_kernel<<<sp3, 256>>>(vz0, vh0, vz1, 0);
    split_chunk_kernel<<<sp2, 256>>>(vh1, vo, vo, 3);

    // ---- layer 0 ----
    build_A_kernel<<<agrid2, 256>>>(x, pz0, ph0);                            // [3]
    apl_hmma_kernel<<<gpair, 256, SMEM_REQ>>>(a0, m0, a1, m1,
                                              bhi + 0 * LSZ, bhi + 1 * LSZ,
                                              zl, hb);                       // [4] profiled
    scan_p1<<<p1_blocks, 256>>>(zl, hb);
    scan_p2<<<p2_blocks, 256>>>();
    scan_p3_norm<<<p3_blocks, 512>>>(zl, hb, h1);

    // ---- layer 1 ----
    build_A_kernel<<<agrid2, 256>>>(h1, pz1, ph1);
    apl_hmma_kernel<<<gpair, 256, SMEM_REQ>>>(a0, m0, a1, m1,
                                              bhi + 2 * LSZ, bhi + 3 * LSZ,
                                              zl, hb);
    scan_p1<<<p1_blocks, 256>>>(zl, hb);
    scan_p2<<<p2_blocks, 256>>>();
    scan_p3_norm<<<p3_blocks, 512>>>(zl, hb, h2);

    // ---- output APL ----
    build_A_kernel<<<agrid1, 256>>>(h2, po, po);
    apl_hmma_kernel<<<gone, 256, SMEM_REQ>>>(a0, m0, a0, m0,
                                             bhi + 4 * LSZ, bhi + 4 * LSZ,
                                             out, out);
}

// round 13
// speedup vs baseline: 1.1970x; 1.0036x over previous
#include <cuda_runtime.h>
#include <cuda_fp16.h>
#include <math.h>
#include <stdint.h>

// Problem constants
#define BD   8
#define TD   2048
#define DD   512
#define NTOT (BD * TD)     // 16384
#define KTOT 4096          // D * P
#define NKC  64            // K-chunks of 64 elements
#define NMT  128           // M-tiles of 128 rows
#define SEG  64
#define SEGLEN (TD / SEG)  // 32

// ---------------------------------------------------------------------------
// Scratch (device globals — no allocations allowed)
// ---------------------------------------------------------------------------
__device__ float g_z[(size_t)NTOT * DD];    // sigmoid(z logits)
__device__ float g_hbar[(size_t)NTOT * DD];
// Pre-swizzled B chunk tiles: [layer][nb(4)][kc(64)] 16KB each
__device__ __align__(128) __half g_bt_hi[5][(size_t)4 * 64 * 8192];
// Compressed 2:4 A tiles: [inst(2)][mt(128)][kc(64)] 8KB each (+1KB metadata)
__device__ __align__(128) __half   g_A[2][(size_t)NMT * NKC * 4096];
__device__ __align__(128) uint8_t g_MM[2][(size_t)NMT * NKC * 1024];
// scan scratch
__device__ float g_scanA[BD * SEG * DD];
__device__ float g_scanB[BD * SEG * DD];
__device__ float g_scanH[BD * SEG * DD];

// ---------------------------------------------------------------------------
// helpers
// ---------------------------------------------------------------------------
__device__ __forceinline__ uint32_t smem_u32(const void* p) {
    uint32_t a;
    asm("{ .reg .u64 t; cvta.to.shared.u64 t, %1; cvt.u32.u64 %0, t; }"
        : "=r"(a) : "l"(p));
    return a;
}

#define SWZ(x) ((x) ^ (((x) >> 3) & 0x70))

__device__ __forceinline__ void mbar_init(uint32_t a, uint32_t cnt) {
    asm volatile("mbarrier.init.shared.b64 [%0], %1;" :: "r"(a), "r"(cnt) : "memory");
}

__device__ __forceinline__ void mbar_wait(uint32_t a, uint32_t ph) {
    asm volatile(
        "{\n\t.reg .pred P;\n\t"
        "W%=:\n\t"
        "mbarrier.try_wait.parity.acquire.cta.shared::cta.b64 P, [%0], %1, 0x989680;\n\t"
        "@P bra.uni D%=;\n\t"
        "bra.uni W%=;\n\t"
        "D%=:\n\t}"
        :: "r"(a), "r"(ph) : "memory");
}

__device__ __forceinline__ void mbar_expect_tx(uint32_t a, uint32_t bytes) {
    asm volatile("mbarrier.arrive.expect_tx.shared.b64 _, [%0], %1;"
                 :: "r"(a), "r"(bytes) : "memory");
}

__device__ __forceinline__ void bulk_ld(uint32_t dst, const void* src,
                                        uint32_t bytes, uint32_t mbar) {
    asm volatile(
        "cp.async.bulk.shared::cluster.global.mbarrier::complete_tx::bytes "
        "[%0], [%1], %2, [%3];"
        :: "r"(dst), "l"(src), "r"(bytes), "r"(mbar) : "memory");
}

// 2:4 compression of the hat pair (1-t @ k, t @ k+1) within an 8-wide i-block.
__device__ __forceinline__ void hat_compress(float x, const float* p,
                                             uint32_t& w0, uint32_t& w1,
                                             uint32_t& mb) {
    int k = 0;
    float pl = p[0], pr = p[1];
#pragma unroll
    for (int j = 1; j <= 6; ++j)
        if (p[j] < x) { k = j; pl = p[j]; pr = p[j + 1]; }
    float t = fminf(fmaxf((x - pl) / (pr - pl), 0.0f), 1.0f);
    __half2 h2 = __floats2half2_rn(1.0f - t, t);
    uint32_t P = *(uint32_t*)&h2;
    uint32_t m0, m1;
    if (k <= 2)      { w0 = P;       w1 = 0u;      m0 = (uint32_t)(k | ((k + 1) << 2)); m1 = 4u; }
    else if (k == 3) { w0 = P << 16; w1 = P >> 16; m0 = 12u;                            m1 = 4u; }
    else             { int kp = k - 4; w0 = 0u; w1 = P; m0 = 4u;
                       m1 = (uint32_t)(kp | ((kp + 1) << 2)); }
    mb = m0 | (m1 << 4);
}

// ---------------------------------------------------------------------------
// split_chunk: v (4096 x 512 f32) -> pre-swizzled 16KB B chunk tiles, fp16.
// ---------------------------------------------------------------------------
__global__ __launch_bounds__(256) void split_chunk_kernel(
    const float* __restrict__ va, const float* __restrict__ vb,
    const float* __restrict__ vc, int ibase) {
    int kc = blockIdx.x, nb = blockIdx.y, z = blockIdx.z;
    const float* v = (z == 0) ? va : (z == 1) ? vb : vc;
    int layer = ibase + z;
    size_t tile_off = ((size_t)layer * 256 + nb * 64 + kc) << 14;  // bytes
    char* hib = (char*)g_bt_hi + tile_off;

    int r = threadIdx.x & 127;
    int chalf = threadIdx.x >> 7;
#pragma unroll
    for (int j = 0; j < 32; ++j) {
        int c = chalf * 32 + j;
        float val = v[(size_t)(kc * 64 + c) * DD + nb * 128 + r];
        uint32_t off = SWZ((uint32_t)(r * 128 + c * 2));
        *(__half*)(hib + off) = __float2half_rn(val);
    }
}

// ---------------------------------------------------------------------------
// build_A_kernel (layer 0 only, from input x)
// ---------------------------------------------------------------------------
__global__ __launch_bounds__(256) void build_A_kernel(
    const float* __restrict__ X, const float* __restrict__ P0,
    const float* __restrict__ P1) {
    int mt = blockIdx.x, kc = blockIdx.y, z = blockIdx.z;
    const float* Pp = z ? P1 : P0;
    char* Ab = (char*)g_A[z] + ((size_t)(mt * NKC + kc) << 13);
    uint8_t* Mb = g_MM[z] + ((size_t)(mt * NKC + kc) << 10);
    int tid = threadIdx.x;
    int il = tid & 7;
    int i = kc * 8 + il;
    float p[8];
#pragma unroll
    for (int j = 0; j < 8; ++j) p[j] = __ldg(&Pp[i * 8 + j]);
    int bm = mt * 128;
#pragma unroll
    for (int q = 0; q < 4; ++q) {
        int n = (tid >> 3) + 32 * q;
        float x = __ldg(&X[(size_t)(bm + n) * DD + i]);
        uint32_t w0, w1, mb;
        hat_compress(x, p, w0, w1, mb);
        uint32_t off = (uint32_t)((n >> 1) * 128 + (n & 1) * 64 +
                                  (il >> 2) * 32 + (il & 3) * 8);
        *(uint2*)(Ab + SWZ(off)) = make_uint2(w0, w1);
        Mb[n * 8 + il] = mb;
    }
}

// ---------------------------------------------------------------------------
// APL sparse-HMMA GEMM. 4-stage bulk-DMA ring of [A 8K][meta 1K][B 16K].
// 256 threads, 8 warps (2Mx4N), warp tile 64x32, CTA 128x128, 2 CTA/SM.
// sigz: apply sigmoid in epilogue for blockIdx.z==0 instance.
// ---------------------------------------------------------------------------
#define STAGE_SZ 25600
#define SMEM_REQ (1024 + 1024 + 4 * STAGE_SZ)

__device__ __forceinline__ void ldsm4(uint32_t a, uint32_t& r0, uint32_t& r1,
                                      uint32_t& r2, uint32_t& r3) {
    asm volatile("ldmatrix.sync.aligned.m8n8.x4.shared.b16 {%0,%1,%2,%3}, [%4];"
                 : "=r"(r0), "=r"(r1), "=r"(r2), "=r"(r3) : "r"(a));
}

__device__ __forceinline__ void mmasp(float* d, const uint32_t* a,
                                      const uint32_t* b, uint32_t e) {
    asm volatile(
        "mma.sp::ordered_metadata.sync.aligned.m16n8k32.row.col.f32.f16.f16.f32 "
        "{%0,%1,%2,%3}, {%4,%5,%6,%7}, {%8,%9,%10,%11}, {%0,%1,%2,%3}, %12, 0x0;"
        : "+f"(d[0]), "+f"(d[1]), "+f"(d[2]), "+f"(d[3])
        : "r"(a[0]), "r"(a[1]), "r"(a[2]), "r"(a[3]),
          "r"(b[0]), "r"(b[1]), "r"(b[2]), "r"(b[3]), "r"(e));
}

__global__ void __launch_bounds__(256, 2) apl_hmma_kernel(
    const __half* __restrict__ A0, const uint8_t* __restrict__ M0,
    const __half* __restrict__ A1, const uint8_t* __restrict__ M1,
    const __half* __restrict__ B0, const __half* __restrict__ B1,
    float* __restrict__ out0, float* __restrict__ out1, int sigz) {
    const int zz = blockIdx.z;
    const char* aSrc = (const char*)(zz ? A1 : A0);
    const char* mSrc = (const char*)(zz ? M1 : M0);
    const __half* Bhi = zz ? B1 : B0;
    float* out = zz ? out1 : out0;
    const int dosig = sigz && (zz == 0);

    extern __shared__ char smem[];
    uint32_t sb = (smem_u32(smem) + 1023u) & ~1023u;
    const uint32_t MB = sb;
    const uint32_t ST = sb + 1024;
    const int tid = threadIdx.x;
    const int lane = tid & 31;
    const int wid = tid >> 5;
    const int wm = wid & 1;
    const int wn = wid >> 1;
    const int mt = blockIdx.x;
    const int nb = blockIdx.y;

    const char* bsrc = (const char*)Bhi + ((size_t)nb * 64 << 14);
    const size_t atile0 = (size_t)mt * NKC;

    if (tid == 0) {
        mbar_init(MB + 0, 1);
        mbar_init(MB + 8, 1);
        mbar_init(MB + 16, 1);
        mbar_init(MB + 24, 1);
        asm volatile("fence.proxy.async.shared::cta;" ::: "memory");
    }
    __syncthreads();

    float acc[4][4][4];
#pragma unroll
    for (int mi = 0; mi < 4; ++mi)
#pragma unroll
        for (int nj = 0; nj < 4; ++nj)
#pragma unroll
            for (int u = 0; u < 4; ++u) acc[mi][nj][u] = 0.0f;

    // hoisted, fully swizzled per-thread offsets (loop-invariant)
    uint32_t swa[4][2], swb[2][4], meo[4][2];
#pragma unroll
    for (int mi = 0; mi < 4; ++mi) {
        int arow = wm * 64 + mi * 16 + (lane & 15);
        uint32_t base = (uint32_t)((arow >> 1) * 128 + (arow & 1) * 64 +
                                   (lane >> 4) * 16);
#pragma unroll
        for (int q = 0; q < 2; ++q) swa[mi][q] = SWZ(base + q * 32);
    }
#pragma unroll
    for (int ni = 0; ni < 2; ++ni) {
        int row = wn * 32 + ni * 16 + (lane & 7) + ((lane & 16) >> 1);
        uint32_t base = (uint32_t)(row * 128 + ((lane >> 3) & 1) * 16);
#pragma unroll
        for (int k4 = 0; k4 < 4; ++k4) swb[ni][k4] = SWZ(base + k4 * 32);
    }
    {
        uint32_t me_t = (uint32_t)((wm * 64 + (lane >> 2)) * 8 + (lane & 1) * 2);
#pragma unroll
        for (int mi = 0; mi < 4; ++mi)
#pragma unroll
            for (int q = 0; q < 2; ++q)
                meo[mi][q] = me_t + (uint32_t)(mi * 128 + q * 4);
    }

    if (tid == 0) {
#pragma unroll
        for (int c = 0; c < 3; ++c) {
            uint32_t stb = ST + c * STAGE_SZ;
            mbar_expect_tx(MB + c * 8, STAGE_SZ);
            bulk_ld(stb, aSrc + ((atile0 + c) << 13), 8192, MB + c * 8);
            bulk_ld(stb + 8192, mSrc + ((atile0 + c) << 10), 1024, MB + c * 8);
            bulk_ld(stb + 9216, bsrc + ((size_t)c << 14), 16384, MB + c * 8);
        }
    }

    for (int kc = 0; kc < NKC; ++kc) {
        int st = kc & 3;
        uint32_t parity = (uint32_t)((kc >> 2) & 1);
        mbar_wait(MB + st * 8, parity);
        __syncthreads();

        if (tid == 0 && kc + 3 < NKC) {
            int s2 = (kc + 3) & 3;
            uint32_t stb = ST + s2 * STAGE_SZ;
            mbar_expect_tx(MB + s2 * 8, STAGE_SZ);
            bulk_ld(stb, aSrc + ((atile0 + kc + 3) << 13), 8192, MB + s2 * 8);
            bulk_ld(stb + 8192, mSrc + ((atile0 + kc + 3) << 10), 1024, MB + s2 * 8);
            bulk_ld(stb + 9216, bsrc + ((size_t)(kc + 3) << 14), 16384, MB + s2 * 8);
        }

        const uint32_t AHc = ST + st * STAGE_SZ;
        const uint32_t MEc = AHc + 8192;
        const uint32_t BHc = AHc + 9216;

        uint32_t metar[4][2];
#pragma unroll
        for (int mi = 0; mi < 4; ++mi)
#pragma unroll
            for (int q = 0; q < 2; ++q) {
                uint32_t base = MEc + meo[mi][q];
                uint32_t lo_, hi_;
                asm volatile("ld.shared.u16 %0, [%1];" : "=r"(lo_) : "r"(base));
                asm volatile("ld.shared.u16 %0, [%1];" : "=r"(hi_) : "r"(base + 64));
                metar[mi][q] = lo_ | (hi_ << 16);
            }

#pragma unroll
        for (int q = 0; q < 2; ++q) {
            uint32_t asp[4][4], bsp[4][4];
#pragma unroll
            for (int mi = 0; mi < 4; ++mi)
                ldsm4(AHc + swa[mi][q],
                      asp[mi][0], asp[mi][1], asp[mi][2], asp[mi][3]);
#pragma unroll
            for (int ni = 0; ni < 2; ++ni) {
                uint32_t r0, r1, r2, r3;
                ldsm4(BHc + swb[ni][2 * q], r0, r1, r2, r3);
                bsp[2 * ni][0] = r0; bsp[2 * ni][1] = r1;
                bsp[2 * ni + 1][0] = r2; bsp[2 * ni + 1][1] = r3;
                ldsm4(BHc + swb[ni][2 * q + 1], r0, r1, r2, r3);
                bsp[2 * ni][2] = r0; bsp[2 * ni][3] = r1;
                bsp[2 * ni + 1][2] = r2; bsp[2 * ni + 1][3] = r3;
            }
#pragma unroll
            for (int mi = 0; mi < 4; ++mi)
#pragma unroll
                for (int nj = 0; nj < 4; ++nj)
                    mmasp(acc[mi][nj], asp[mi], bsp[nj], metar[mi][q]);
        }
    }

    // epilogue (optional fused sigmoid for the z instance)
#pragma unroll
    for (int mi = 0; mi < 4; ++mi) {
#pragma unroll
        for (int nj = 0; nj < 4; ++nj) {
            float v0 = acc[mi][nj][0], v1 = acc[mi][nj][1];
            float v2 = acc[mi][nj][2], v3 = acc[mi][nj][3];
            if (dosig) {
                v0 = 1.0f / (1.0f + __expf(-v0));
                v1 = 1.0f / (1.0f + __expf(-v1));
                v2 = 1.0f / (1.0f + __expf(-v2));
                v3 = 1.0f / (1.0f + __expf(-v3));
            }
            int row = mt * 128 + wm * 64 + mi * 16 + (lane >> 2);
            int col = nb * 128 + wn * 32 + nj * 8 + 2 * (lane & 3);
            *(float2*)&out[(size_t)row * DD + col] = make_float2(v0, v1);
            *(float2*)&out[(size_t)(row + 8) * DD + col] = make_float2(v2, v3);
        }
    }
}

// ---------------------------------------------------------------------------
// Segmented scan, SEG=64 (z already sigmoided).
// ---------------------------------------------------------------------------
__global__ __launch_bounds__(256) void scan_p1(
    const float* __restrict__ z, const float* __restrict__ hb) {
    int gid = blockIdx.x * blockDim.x + threadIdx.x;
    if (gid >= BD * SEG * DD) return;
    int d = gid & 511;
    int bs = gid >> 9;
    int seg = bs & (SEG - 1);
    int b = bs / SEG;
    size_t base = (size_t)b * TD * DD + (size_t)seg * SEGLEN * DD + d;
    float A = 1.0f, Bv = 0.0f;
#pragma unroll 8
    for (int t = 0; t < SEGLEN; ++t) {
        size_t idx = base + (size_t)t * DD;
        float zv = z[idx];
        float a = 1.0f - zv;
        float bb = zv * hb[idx];
        A *= a;
        Bv = fmaf(a, Bv, bb);
    }
    g_scanA[gid] = A;
    g_scanB[gid] = Bv;
}

__global__ __launch_bounds__(256) void scan_p2() {
    int c = blockIdx.x * blockDim.x + threadIdx.x;
    if (c >= BD * DD) return;
    int d = c & 511;
    int b = c >> 9;
    float h = 0.0f;
#pragma unroll
    for (int seg = 0; seg < SEG; ++seg) {
        int gid = ((b * SEG + seg) << 9) + d;
        g_scanH[gid] = h;
        h = fmaf(g_scanA[gid], h, g_scanB[gid]);
    }
}

// p3 + maxabs norm + FUSED next-layer compressed-A build (nsets param sets).
// block = 512 threads = all d of one (b, seg).
__global__ __launch_bounds__(512) void scan_p3_norm_fuse(
    const float* __restrict__ z, const float* __restrict__ hb,
    float* __restrict__ h, const float* __restrict__ P0,
    const float* __restrict__ P1, int nsets) {
    __shared__ float red[34];
    int blk = blockIdx.x;
    int d = threadIdx.x;
    int seg = blk & (SEG - 1);
    int b = blk / SEG;
    int lane = d & 31, wid = d >> 5;
    size_t base = (size_t)b * TD * DD + (size_t)seg * SEGLEN * DD + d;
    float hc = g_scanH[(blk << 9) + d];

    // next-layer hat params for feature i = d
    float p0[8], p1[8];
#pragma unroll
    for (int j = 0; j < 8; ++j) p0[j] = __ldg(&P0[d * 8 + j]);
    if (nsets > 1) {
#pragma unroll
        for (int j = 0; j < 8; ++j) p1[j] = __ldg(&P1[d * 8 + j]);
    }
    const int il = d & 7;
    const int kc = d >> 3;
    const int n0g = b * TD + seg * SEGLEN;       // first token of this block
    const int mt = n0g >> 7;
    const int nnb = n0g & 127;                   // 32-aligned, stays in tile
    char* Ab0 = (char*)g_A[0] + ((size_t)(mt * NKC + kc) << 13);
    uint8_t* Mb0 = g_MM[0] + ((size_t)(mt * NKC + kc) << 10);
    char* Ab1 = (char*)g_A[1] + ((size_t)(mt * NKC + kc) << 13);
    uint8_t* Mb1 = g_MM[1] + ((size_t)(mt * NKC + kc) << 10);
    const uint32_t ilo = (uint32_t)((il >> 2) * 32 + (il & 3) * 8);

    for (int t = 0; t < SEGLEN; ++t) {
        size_t idx = base + (size_t)t * DD;
        float zv = z[idx];
        hc = fmaf(zv, hb[idx] - hc, hc);
        int slot = (t & 1) * 17;
        float m = fabsf(hc);
#pragma unroll
        for (int o = 16; o; o >>= 1)
            m = fmaxf(m, __shfl_xor_sync(0xffffffffu, m, o));
        if (lane == 0) red[slot + wid] = m;
        __syncthreads();
        if (wid == 0) {
            float mm = red[slot + (lane & 15)];
#pragma unroll
            for (int o = 8; o; o >>= 1)
                mm = fmaxf(mm, __shfl_xor_sync(0xffffffffu, mm, o));
            if (lane == 0) red[slot + 16] = mm;
        }
        __syncthreads();
        float inv = 1.0f / (red[slot + 16] + 1e-6f);
        float hn = hc * inv;
        h[idx] = hn;

        // fused next-layer A build for this (token, feature)
        int nn = nnb + t;
        uint32_t aoff = SWZ((uint32_t)((nn >> 1) * 128 + (nn & 1) * 64) + ilo);
        uint32_t w0, w1, mb;
        hat_compress(hn, p0, w0, w1, mb);
        *(uint2*)(Ab0 + aoff) = make_uint2(w0, w1);
        Mb0[nn * 8 + il] = (uint8_t)mb;
        if (nsets > 1) {
            hat_compress(hn, p1, w0, w1, mb);
            *(uint2*)(Ab1 + aoff) = make_uint2(w0, w1);
            Mb1[nn * 8 + il] = (uint8_t)mb;
        }
    }
}

// ---------------------------------------------------------------------------
// kernel_launch (launch #4 = paired apl_hmma for the ncu capture window)
// ---------------------------------------------------------------------------
extern "C" void kernel_launch(void* const* d_in, const int* in_sizes, int n_in,
                              void* d_out, int out_size) {
    const float* x   = (const float*)d_in[0];
    const float* pz0 = (const float*)d_in[1];
    const float* vz0 = (const float*)d_in[2];
    const float* ph0 = (const float*)d_in[3];
    const float* vh0 = (const float*)d_in[4];
    const float* pz1 = (const float*)d_in[5];
    const float* vz1 = (const float*)d_in[6];
    const float* ph1 = (const float*)d_in[7];
    const float* vh1 = (const float*)d_in[8];
    const float* po  = (const float*)d_in[9];
    const float* vo  = (const float*)d_in[10];

    const int N = in_sizes[0] / DD;  // 16384

    float *zb, *hb;
    __half *bhi, *a0, *a1;
    uint8_t *m0, *m1;
    cudaGetSymbolAddress((void**)&zb, g_z);
    cudaGetSymbolAddress((void**)&hb, g_hbar);
    cudaGetSymbolAddress((void**)&bhi, g_bt_hi);
    cudaGetSymbolAddress((void**)&a0, g_A);
    cudaGetSymbolAddress((void**)&m0, g_MM);
    a1 = a0 + (size_t)NMT * NKC * 4096;
    m1 = m0 + (size_t)NMT * NKC * 1024;

    static int smem_set = 0;
    if (!smem_set) {
        cudaFuncSetAttribute(apl_hmma_kernel,
                             cudaFuncAttributeMaxDynamicSharedMemorySize, SMEM_REQ);
        smem_set = 1;
    }

    float* out = (float*)d_out;
    float* h1  = out + (size_t)N * DD;
    float* h2  = h1 + (size_t)N * DD;

    dim3 sp3(64, 4, 3);
    dim3 sp2(64, 4, 2);
    dim3 agrid2(NMT, NKC, 2);
    dim3 gpair(NMT, 4, 2);
    dim3 gone(NMT, 4, 1);
    const int p1_blocks = (BD * SEG * DD + 255) / 256;
    const int p2_blocks = (BD * DD + 255) / 256;
    const int p3_blocks = BD * SEG;
    const size_t LSZ = (size_t)4 * 64 * 8192;

    // [1][2] pre-stage all V into chunked/pre-swizzled fp16 B tiles
    split_chunk_kernel<<<sp3, 256>>>(vz0, vh0, vz1, 0);
    split_chunk_kernel<<<sp2, 256>>>(vh1, vo, vo, 3);

    // ---- layer 0 ----
    build_A_kernel<<<agrid2, 256>>>(x, pz0, ph0);                            // [3]
    apl_hmma_kernel<<<gpair, 256, SMEM_REQ>>>(a0, m0, a1, m1,
                                              bhi + 0 * LSZ, bhi + 1 * LSZ,
                                              zb, hb, 1);                    // [4] profiled
    scan_p1<<<p1_blocks, 256>>>(zb, hb);
    scan_p2<<<p2_blocks, 256>>>();
    scan_p3_norm_fuse<<<p3_blocks, 512>>>(zb, hb, h1, pz1, ph1, 2);

    // ---- layer 1 (A tiles already built by fused p3) ----
    apl_hmma_kernel<<<gpair, 256, SMEM_REQ>>>(a0, m0, a1, m1,
                                              bhi + 2 * LSZ, bhi + 3 * LSZ,
                                              zb, hb, 1);
    scan_p1<<<p1_blocks, 256>>>(zb, hb);
    scan_p2<<<p2_blocks, 256>>>();
    scan_p3_norm_fuse<<<p3_blocks, 512>>>(zb, hb, h2, po, po, 1);

    // ---- output APL (A tiles built by fused p3) ----
    apl_hmma_kernel<<<gone, 256, SMEM_REQ>>>(a0, m0, a0, m0,
                                             bhi + 4 * LSZ, bhi + 4 * LSZ,
                                             out, out, 0);
}